// round 4
// baseline (speedup 1.0000x reference)
#include <cuda_runtime.h>
#include <math.h>

#define LSEQ 2048
#define DMODEL 512
#define NH 8
#define HD 64
#define NFFT 4096
#define EPSF 1e-5f
#define NCHUNK 16
#define TCH 128

// ---------------- scratch (device globals; no runtime allocation) ----------------
__device__ float g_q[LSEQ * DMODEL];
__device__ float g_k[LSEQ * DMODEL];
__device__ float g_v[LSEQ * DMODEL];
__device__ float g_filt[LSEQ * DMODEL];
__device__ float g_kf[LSEQ * DMODEL];
__device__ float g_vf[LSEQ * DMODEL];
__device__ float g_gate[NH * LSEQ];
__device__ float g_S[NH * NCHUNK * HD * HD];
__device__ float g_Spre[NH * NCHUNK * HD * HD];
__device__ float g_Gpre[NH * NCHUNK];
__device__ float g_sraw[LSEQ * DMODEL];

// ---------------- generic GEMM: C[m,n] = sum_k A[m,k]*W[n,k] + bias[n] ----------------
__global__ void gemm_bias_kernel(const float* __restrict__ A, const float* __restrict__ W,
                                 const float* __restrict__ bias, float* __restrict__ C,
                                 int M, int N, int K) {
    __shared__ float As[16][68];
    __shared__ float Ws[16][68];
    int tid = threadIdx.x;                 // 256 threads
    int bm = blockIdx.y * 64, bn = blockIdx.x * 64;
    int row = tid >> 2, kc = (tid & 3) << 2;
    int tx = tid & 15, ty = tid >> 4;
    float acc[4][4];
#pragma unroll
    for (int i = 0; i < 4; i++)
#pragma unroll
        for (int j = 0; j < 4; j++) acc[i][j] = 0.f;

    for (int k0 = 0; k0 < K; k0 += 16) {
        float4 a4 = *reinterpret_cast<const float4*>(A + (size_t)(bm + row) * K + k0 + kc);
        float4 w4 = *reinterpret_cast<const float4*>(W + (size_t)(bn + row) * K + k0 + kc);
        As[kc + 0][row] = a4.x; As[kc + 1][row] = a4.y; As[kc + 2][row] = a4.z; As[kc + 3][row] = a4.w;
        Ws[kc + 0][row] = w4.x; Ws[kc + 1][row] = w4.y; Ws[kc + 2][row] = w4.z; Ws[kc + 3][row] = w4.w;
        __syncthreads();
#pragma unroll
        for (int kk = 0; kk < 16; kk++) {
            float a[4], b[4];
#pragma unroll
            for (int i = 0; i < 4; i++) { a[i] = As[kk][ty * 4 + i]; b[i] = Ws[kk][tx * 4 + i]; }
#pragma unroll
            for (int i = 0; i < 4; i++)
#pragma unroll
                for (int j = 0; j < 4; j++) acc[i][j] += a[i] * b[j];
        }
        __syncthreads();
    }
#pragma unroll
    for (int i = 0; i < 4; i++) {
        float4 c4;
        c4.x = acc[i][0] + bias[bn + tx * 4 + 0];
        c4.y = acc[i][1] + bias[bn + tx * 4 + 1];
        c4.z = acc[i][2] + bias[bn + tx * 4 + 2];
        c4.w = acc[i][3] + bias[bn + tx * 4 + 3];
        *reinterpret_cast<float4*>(C + (size_t)(bm + ty * 4 + i) * N + bn + tx * 4) = c4;
    }
}

// ---------------- per-(l,head) L2 norm of k and v, in place ----------------
__global__ void l2norm_kv_kernel() {
    __shared__ float red[512];
    int l = blockIdx.x, tid = threadIdx.x;  // 512 threads
    float kv = g_k[l * DMODEL + tid];
    red[tid] = kv * kv;
    __syncthreads();
#pragma unroll
    for (int o = 32; o >= 1; o >>= 1) {
        if ((tid & 63) < o) red[tid] += red[tid + o];
        __syncthreads();
    }
    float nk = sqrtf(red[tid & ~63]);
    g_k[l * DMODEL + tid] = kv / fmaxf(nk, EPSF);
    __syncthreads();
    float vv = g_v[l * DMODEL + tid];
    red[tid] = vv * vv;
    __syncthreads();
#pragma unroll
    for (int o = 32; o >= 1; o >>= 1) {
        if ((tid & 63) < o) red[tid] += red[tid + o];
        __syncthreads();
    }
    float nv = sqrtf(red[tid & ~63]);
    g_v[l * DMODEL + tid] = vv / fmaxf(nv, EPSF);
}

// ---------------- radix-2 DIT FFT over 4096 complex points in smem ----------------
__device__ __forceinline__ void fft12(float2* A, const float2* TW) {
    for (int s = 1; s <= 12; s++) {
        int half = 1 << (s - 1);
        int sh = 12 - s;
        __syncthreads();
        for (int j = threadIdx.x; j < NFFT / 2; j += 512) {
            int p = j & (half - 1);
            int base = ((j >> (s - 1)) << s) + p;
            float2 w = TW[p << sh];
            float2 a = A[base], b = A[base + half];
            float tr = w.x * b.x - w.y * b.y;
            float ti = w.x * b.y + w.y * b.x;
            A[base]        = make_float2(a.x + tr, a.y + ti);
            A[base + half] = make_float2(a.x - tr, a.y - ti);
        }
    }
    __syncthreads();
}

// Causal conv via FFT. Packs (k_norm + i*v_norm) per channel into ONE complex FFT,
// multiplies by the (shared) filter spectrum, inverse-FFTs: Re -> k_f, Im -> v_f.
// One block per channel c = h*64+d (columns of the [L, D] projections).
__global__ void fftconv_kernel() {
    extern __shared__ float2 smf[];
    float2* F  = smf;
    float2* Zs = smf + NFFT;
    float2* TW = smf + 2 * NFFT;
    int c = blockIdx.x, tid = threadIdx.x;  // 512 threads

    for (int t = tid; t < NFFT / 2; t += 512) {
        float s, co;
        __sincosf(-6.283185307179586f * (float)t / (float)NFFT, &s, &co);
        TW[t] = make_float2(co, s);
    }
    // filter FFT (real input), bit-reversed load
    for (int i = tid; i < NFFT; i += 512) {
        int r = __brev(i) >> 20;
        float val = (r < LSEQ) ? g_filt[r * DMODEL + c] : 0.f;
        F[i] = make_float2(val, 0.f);
    }
    fft12(F, TW);
    // z = k + i*v, bit-reversed load
    for (int i = tid; i < NFFT; i += 512) {
        int r = __brev(i) >> 20;
        float kr = 0.f, vi = 0.f;
        if (r < LSEQ) { kr = g_k[r * DMODEL + c]; vi = g_v[r * DMODEL + c]; }
        Zs[i] = make_float2(kr, vi);
    }
    fft12(Zs, TW);
    // pointwise multiply, conjugate (IFFT = conj(FFT(conj(x)))/N), re-bit-reverse
    float2 y[8];
#pragma unroll
    for (int jj = 0; jj < 8; jj++) {
        int i = tid + jj * 512;
        float2 z = Zs[i], f = F[i];
        float pr = z.x * f.x - z.y * f.y;
        float pi = z.x * f.y + z.y * f.x;
        y[jj] = make_float2(pr, -pi);
    }
    __syncthreads();
#pragma unroll
    for (int jj = 0; jj < 8; jj++) {
        int i = tid + jj * 512;
        Zs[__brev(i) >> 20] = y[jj];
    }
    fft12(Zs, TW);
    const float invN = 1.f / (float)NFFT;
    for (int t = tid; t < LSEQ; t += 512) {
        float2 w = Zs[t];
        g_kf[t * DMODEL + c] =  w.x * invN;   // Re(conj) = Re
        g_vf[t * DMODEL + c] = -w.y * invN;   // Im(conj) = -Im
    }
}

// ---------------- gates: g_l = relu(v_f^T (W .* scale) k_f + b)^2 + eps ----------------
__global__ void gates_kernel(const float* __restrict__ wgz_w, const float* __restrict__ wgz_b,
                             const float* __restrict__ scale) {
    __shared__ float Wsc[HD * HD];
    int tid = threadIdx.x;  // 256
    for (int i = tid; i < HD * HD; i += blockDim.x) Wsc[i] = wgz_w[i] * scale[i];
    __syncthreads();
    int w = tid >> 5, lane = tid & 31;
    int p = blockIdx.x * 8 + w;           // p = h*2048 + l
    int h = p >> 11, l = p & (LSEQ - 1);
    const float* vrow = g_vf + l * DMODEL + h * HD;
    const float* krow = g_kf + l * DMODEL + h * HD;
    float acc = 0.f;
#pragma unroll
    for (int eo = 0; eo < 2; eo++) {
        int e = lane + eo * 32;
        float inner = 0.f;
#pragma unroll 16
        for (int d = 0; d < 64; d++) inner += vrow[d] * Wsc[d * 64 + e];
        acc += krow[e] * inner;
    }
#pragma unroll
    for (int o = 16; o; o >>= 1) acc += __shfl_xor_sync(0xffffffffu, acc, o);
    if (lane == 0) {
        float lg = acc + wgz_b[0];
        float r = fmaxf(lg, 0.f);
        g_gate[p] = r * r + EPSF;
    }
}

// ---------------- per-chunk rank-1 sums: S_c[d,e] = sum_{l in chunk} g_l v_f[l,d] k_f[l,e] ----
__global__ void chunksum_kernel() {
    int hb = blockIdx.x;                  // h*16 + c
    int h = hb >> 4, c = hb & 15;
    int tid = threadIdx.x;                // 128
    int e = tid >> 1, half = tid & 1, d0 = half * 32;
    float acc[32];
#pragma unroll
    for (int j = 0; j < 32; j++) acc[j] = 0.f;
    int l0 = c * TCH;
    for (int i = 0; i < TCH; i++) {
        int l = l0 + i;
        float gg = g_gate[h * LSEQ + l];
        float ke = g_kf[l * DMODEL + h * HD + e];
        float gk = gg * ke;
        const float4* vp = reinterpret_cast<const float4*>(g_vf + l * DMODEL + h * HD + d0);
#pragma unroll
        for (int j4 = 0; j4 < 8; j4++) {
            float4 v4 = vp[j4];
            acc[j4 * 4 + 0] += gk * v4.x;
            acc[j4 * 4 + 1] += gk * v4.y;
            acc[j4 * 4 + 2] += gk * v4.z;
            acc[j4 * 4 + 3] += gk * v4.w;
        }
    }
    float* Sp = g_S + (size_t)hb * HD * HD;
#pragma unroll
    for (int j = 0; j < 32; j++) Sp[(d0 + j) * 64 + e] = acc[j];
}

// ---------------- exclusive prefix over chunks (state matrices + gate sums) ----------------
__global__ void prefix_kernel() {
    int h = blockIdx.x, tid = threadIdx.x;  // 512
    __shared__ float gc[NCHUNK];
    if (tid < NCHUNK) {
        float s = 0.f;
        for (int i = 0; i < TCH; i++) s += g_gate[h * LSEQ + tid * TCH + i];
        gc[tid] = s;
    }
    __syncthreads();
    if (tid == 0) {
        float run = 0.f;
        for (int c = 0; c < NCHUNK; c++) { float t = gc[c]; g_Gpre[h * NCHUNK + c] = run; run += t; }
    }
    for (int idx = tid; idx < HD * HD; idx += 512) {
        float run = 0.f;
#pragma unroll
        for (int c = 0; c < NCHUNK; c++) {
            size_t off = ((size_t)(h * NCHUNK + c)) * HD * HD + idx;
            float t = g_S[off];
            g_Spre[off] = run;
            run += t;
        }
    }
}

// ---------------- intra-chunk scan + readout: s_e(l) = q . (scale .* M_l) / max(G_l, eps) ----
__global__ void scan_readout_kernel(const float* __restrict__ scale) {
    extern __shared__ float sm[];
    float* qs = sm;                // 128*64
    float* ks = sm + 8192;
    float* vs = sm + 16384;
    float* gs = sm + 24576;        // 128
    int hb = blockIdx.x;
    int h = hb >> 4, c = hb & 15;
    int tid = threadIdx.x;         // 128
    int l0 = c * TCH;
    for (int idx = tid; idx < TCH * HD; idx += 128) {
        int row = idx >> 6, col = idx & 63;
        int ga = (l0 + row) * DMODEL + h * HD + col;
        qs[idx] = g_q[ga];
        ks[idx] = g_kf[ga];
        vs[idx] = g_vf[ga];
    }
    gs[tid] = g_gate[h * LSEQ + l0 + tid];
    int e = tid >> 1, half = tid & 1, d0 = half * 32;
    float M[32], sc[32];
    {
        const float* Sp = g_Spre + (size_t)hb * HD * HD;
#pragma unroll
        for (int j = 0; j < 32; j++) {
            M[j]  = Sp[(d0 + j) * 64 + e];
            sc[j] = scale[(d0 + j) * 64 + e];
        }
    }
    float G = g_Gpre[h * NCHUNK + c];
    __syncthreads();
    const float4* q4 = reinterpret_cast<const float4*>(qs);
    const float4* v4 = reinterpret_cast<const float4*>(vs);
    int o4 = half * 8;
    for (int i = 0; i < TCH; i++) {
        float gg = gs[i]; G += gg;
        float ke = ks[i * HD + e];
        float gk = gg * ke;
        float r = 0.f;
#pragma unroll
        for (int j4 = 0; j4 < 8; j4++) {
            float4 vv = v4[i * 16 + o4 + j4];
            float4 qq = q4[i * 16 + o4 + j4];
            int jb = j4 * 4;
            M[jb + 0] += gk * vv.x; r += qq.x * (sc[jb + 0] * M[jb + 0]);
            M[jb + 1] += gk * vv.y; r += qq.y * (sc[jb + 1] * M[jb + 1]);
            M[jb + 2] += gk * vv.z; r += qq.z * (sc[jb + 2] * M[jb + 2]);
            M[jb + 3] += gk * vv.w; r += qq.w * (sc[jb + 3] * M[jb + 3]);
        }
        r += __shfl_xor_sync(0xffffffffu, r, 1);
        if (half == 0) g_sraw[(l0 + i) * DMODEL + h * HD + e] = r / fmaxf(G, EPSF);
    }
}

// ---------------- l2-normalize sp per (l, head), in place ----------------
__global__ void spnorm_kernel() {
    int tid = threadIdx.x;          // 256
    int w = tid >> 5, lane = tid & 31;
    int p = blockIdx.x * 8 + w;     // l*8 + h
    int l = p >> 3, h = p & 7;
    float* base = g_sraw + l * DMODEL + h * HD;
    float a = base[lane], b = base[lane + 32];
    float ss = a * a + b * b;
#pragma unroll
    for (int o = 16; o; o >>= 1) ss += __shfl_xor_sync(0xffffffffu, ss, o);
    float inv = 1.f / fmaxf(sqrtf(ss), EPSF);
    base[lane] = a * inv;
    base[lane + 32] = b * inv;
}

// ---------------- launch ----------------
extern "C" void kernel_launch(void* const* d_in, const int* in_sizes, int n_in,
                              void* d_out, int out_size) {
    const float* x     = (const float*)d_in[0];
    const float* sb    = (const float*)d_in[1];
    const float* wq_w  = (const float*)d_in[2];
    const float* wq_b  = (const float*)d_in[3];
    const float* wk_w  = (const float*)d_in[4];
    const float* wk_b  = (const float*)d_in[5];
    const float* wv_w  = (const float*)d_in[6];
    const float* wv_b  = (const float*)d_in[7];
    const float* wo_w  = (const float*)d_in[8];
    const float* wo_b  = (const float*)d_in[9];
    const float* td_w  = (const float*)d_in[10];
    const float* td_b  = (const float*)d_in[11];
    const float* wgz_w = (const float*)d_in[12];
    const float* wgz_b = (const float*)d_in[13];
    const float* kvs   = (const float*)d_in[14];
    float* out = (float*)d_out;

    float *qp, *kp, *vp, *fp, *sp;
    cudaGetSymbolAddress((void**)&qp, g_q);
    cudaGetSymbolAddress((void**)&kp, g_k);
    cudaGetSymbolAddress((void**)&vp, g_v);
    cudaGetSymbolAddress((void**)&fp, g_filt);
    cudaGetSymbolAddress((void**)&sp, g_sraw);

    cudaFuncSetAttribute(fftconv_kernel, cudaFuncAttributeMaxDynamicSharedMemorySize, 81920);
    cudaFuncSetAttribute(scan_readout_kernel, cudaFuncAttributeMaxDynamicSharedMemorySize, 98816);

    dim3 gg(DMODEL / 64, LSEQ / 64);
    gemm_bias_kernel<<<gg, 256>>>(x,  wq_w, wq_b, qp, LSEQ, DMODEL, DMODEL);
    gemm_bias_kernel<<<gg, 256>>>(x,  wk_w, wk_b, kp, LSEQ, DMODEL, DMODEL);
    gemm_bias_kernel<<<gg, 256>>>(x,  wv_w, wv_b, vp, LSEQ, DMODEL, DMODEL);
    gemm_bias_kernel<<<gg, 256>>>(sb, td_w, td_b, fp, LSEQ, DMODEL, DMODEL);
    l2norm_kv_kernel<<<LSEQ, 512>>>();
    fftconv_kernel<<<DMODEL, 512, 81920>>>();
    gates_kernel<<<(NH * LSEQ) / 8, 256>>>(wgz_w, wgz_b, kvs);
    chunksum_kernel<<<NH * NCHUNK, 128>>>();
    prefix_kernel<<<NH, 512>>>();
    scan_readout_kernel<<<NH * NCHUNK, 128, 98816>>>(kvs);
    spnorm_kernel<<<(LSEQ * NH) / 8, 256>>>();
    gemm_bias_kernel<<<gg, 256>>>(sp, wo_w, wo_b, out, LSEQ, DMODEL, DMODEL);
}

// round 5
// speedup vs baseline: 1.1062x; 1.1062x over previous
#include <cuda_runtime.h>
#include <math.h>

#define LSEQ 2048
#define DMODEL 512
#define NH 8
#define HD 64
#define NFFT 4096
#define EPSF 1e-5f
#define NCHUNK 16
#define TCH 128

// ---------------- scratch (device globals; no runtime allocation) ----------------
__device__ float g_q[LSEQ * DMODEL];
__device__ float g_k[LSEQ * DMODEL];
__device__ float g_v[LSEQ * DMODEL];
__device__ float g_filt[LSEQ * DMODEL];
__device__ float g_kf[LSEQ * DMODEL];
__device__ float g_vf[LSEQ * DMODEL];
__device__ float g_gate[NH * LSEQ];
__device__ float g_S[NH * NCHUNK * HD * HD];
__device__ float g_Spre[NH * NCHUNK * HD * HD];
__device__ float g_Gpre[NH * NCHUNK];
__device__ float g_sraw[LSEQ * DMODEL];
__device__ float2 g_Ff[(DMODEL / 2) * NFFT];   // packed filter spectra (2 channels/FFT)

// ---------------- double-buffered GEMM body: C[m,n] = sum_k A[m,k]*W[n,k] + bias[n] -------
// 64x64 tile, 256 threads, 4x4 acc, K=N=512 fixed. One sync per 16-wide K tile.
__device__ __forceinline__ void gemm_body(const float* __restrict__ A, const float* __restrict__ W,
                                          const float* __restrict__ bias, float* __restrict__ C) {
    __shared__ float As[2][16][68];
    __shared__ float Ws[2][16][68];
    int tid = threadIdx.x;                 // 256 threads
    int bm = blockIdx.y * 64, bn = blockIdx.x * 64;
    int row = tid >> 2, kc = (tid & 3) << 2;
    int tx = tid & 15, ty = tid >> 4;
    const float* Ap = A + (size_t)(bm + row) * DMODEL + kc;
    const float* Wp = W + (size_t)(bn + row) * DMODEL + kc;

    float acc[4][4];
#pragma unroll
    for (int i = 0; i < 4; i++)
#pragma unroll
        for (int j = 0; j < 4; j++) acc[i][j] = 0.f;

    // preload tile 0
    {
        float4 a4 = *reinterpret_cast<const float4*>(Ap);
        float4 w4 = *reinterpret_cast<const float4*>(Wp);
        As[0][kc + 0][row] = a4.x; As[0][kc + 1][row] = a4.y; As[0][kc + 2][row] = a4.z; As[0][kc + 3][row] = a4.w;
        Ws[0][kc + 0][row] = w4.x; Ws[0][kc + 1][row] = w4.y; Ws[0][kc + 2][row] = w4.z; Ws[0][kc + 3][row] = w4.w;
    }
    __syncthreads();

    int buf = 0;
    for (int k0 = 16; k0 <= DMODEL; k0 += 16) {
        float4 a4n, w4n;
        bool more = (k0 < DMODEL);
        if (more) {
            a4n = *reinterpret_cast<const float4*>(Ap + k0);
            w4n = *reinterpret_cast<const float4*>(Wp + k0);
        }
#pragma unroll
        for (int kk = 0; kk < 16; kk++) {
            float a[4], b[4];
#pragma unroll
            for (int i = 0; i < 4; i++) { a[i] = As[buf][kk][ty * 4 + i]; b[i] = Ws[buf][kk][tx * 4 + i]; }
#pragma unroll
            for (int i = 0; i < 4; i++)
#pragma unroll
                for (int j = 0; j < 4; j++) acc[i][j] += a[i] * b[j];
        }
        if (more) {
            int nb = buf ^ 1;
            As[nb][kc + 0][row] = a4n.x; As[nb][kc + 1][row] = a4n.y; As[nb][kc + 2][row] = a4n.z; As[nb][kc + 3][row] = a4n.w;
            Ws[nb][kc + 0][row] = w4n.x; Ws[nb][kc + 1][row] = w4n.y; Ws[nb][kc + 2][row] = w4n.z; Ws[nb][kc + 3][row] = w4n.w;
            __syncthreads();
        }
        buf ^= 1;
    }
#pragma unroll
    for (int i = 0; i < 4; i++) {
        float4 c4;
        c4.x = acc[i][0] + bias[bn + tx * 4 + 0];
        c4.y = acc[i][1] + bias[bn + tx * 4 + 1];
        c4.z = acc[i][2] + bias[bn + tx * 4 + 2];
        c4.w = acc[i][3] + bias[bn + tx * 4 + 3];
        *reinterpret_cast<float4*>(C + (size_t)(bm + ty * 4 + i) * DMODEL + bn + tx * 4) = c4;
    }
}

// fused Q/K/V/filter projections: blockIdx.z selects the GEMM (1024 blocks total)
__global__ __launch_bounds__(256) void gemm4_kernel(
    const float* __restrict__ x, const float* __restrict__ sb,
    const float* __restrict__ Wq, const float* __restrict__ Wk,
    const float* __restrict__ Wv, const float* __restrict__ Wt,
    const float* __restrict__ bq, const float* __restrict__ bk,
    const float* __restrict__ bv, const float* __restrict__ bt) {
    int z = blockIdx.z;
    const float* A = (z == 3) ? sb : x;
    const float* W = (z == 0) ? Wq : (z == 1) ? Wk : (z == 2) ? Wv : Wt;
    const float* b = (z == 0) ? bq : (z == 1) ? bk : (z == 2) ? bv : bt;
    float* C = (z == 0) ? g_q : (z == 1) ? g_k : (z == 2) ? g_v : g_filt;
    gemm_body(A, W, b, C);
}

__global__ __launch_bounds__(256) void gemm1_kernel(const float* __restrict__ A, const float* __restrict__ W,
                                                    const float* __restrict__ bias, float* __restrict__ C) {
    gemm_body(A, W, bias, C);
}

// ---------------- per-(l,head) L2 norm of k and v, in place ----------------
__global__ void l2norm_kv_kernel() {
    __shared__ float red[512];
    int l = blockIdx.x, tid = threadIdx.x;  // 512 threads
    float kv = g_k[l * DMODEL + tid];
    red[tid] = kv * kv;
    __syncthreads();
#pragma unroll
    for (int o = 32; o >= 1; o >>= 1) {
        if ((tid & 63) < o) red[tid] += red[tid + o];
        __syncthreads();
    }
    float nk = sqrtf(red[tid & ~63]);
    g_k[l * DMODEL + tid] = kv / fmaxf(nk, EPSF);
    __syncthreads();
    float vv = g_v[l * DMODEL + tid];
    red[tid] = vv * vv;
    __syncthreads();
#pragma unroll
    for (int o = 32; o >= 1; o >>= 1) {
        if ((tid & 63) < o) red[tid] += red[tid + o];
        __syncthreads();
    }
    float nv = sqrtf(red[tid & ~63]);
    g_v[l * DMODEL + tid] = vv / fmaxf(nv, EPSF);
}

// ---------------- radix-2 DIT FFT over 4096 complex points in smem ----------------
__device__ __forceinline__ void fft12(float2* A, const float2* TW) {
    for (int s = 1; s <= 12; s++) {
        int half = 1 << (s - 1);
        int sh = 12 - s;
        __syncthreads();
        for (int j = threadIdx.x; j < NFFT / 2; j += 512) {
            int p = j & (half - 1);
            int base = ((j >> (s - 1)) << s) + p;
            float2 w = TW[p << sh];
            float2 a = A[base], b = A[base + half];
            float tr = w.x * b.x - w.y * b.y;
            float ti = w.x * b.y + w.y * b.x;
            A[base]        = make_float2(a.x + tr, a.y + ti);
            A[base + half] = make_float2(a.x - tr, a.y - ti);
        }
    }
    __syncthreads();
}

__device__ __forceinline__ void make_tw(float2* TW) {
    for (int t = threadIdx.x; t < NFFT / 2; t += 512) {
        float s, co;
        __sincosf(-6.283185307179586f * (float)t / (float)NFFT, &s, &co);
        TW[t] = make_float2(co, s);
    }
}

// Precompute filter spectra: one complex FFT per CHANNEL PAIR (f_{2p} + i f_{2p+1}).
// Stores the packed spectrum; separation happens in the conv kernel via conjugate symmetry.
__global__ void filtfft_kernel() {
    extern __shared__ float2 smf[];
    float2* F  = smf;              // 4096
    float2* TW = smf + NFFT;       // 2048
    int p = blockIdx.x, tid = threadIdx.x;  // 512 threads, 256 blocks
    int c0 = 2 * p;
    make_tw(TW);
    for (int i = tid; i < NFFT; i += 512) {
        int r = __brev(i) >> 20;
        float v0 = 0.f, v1 = 0.f;
        if (r < LSEQ) { v0 = g_filt[r * DMODEL + c0]; v1 = g_filt[r * DMODEL + c0 + 1]; }
        F[i] = make_float2(v0, v1);
    }
    fft12(F, TW);
    float2* Gp = g_Ff + (size_t)p * NFFT;
    for (int t = tid; t < NFFT; t += 512) Gp[t] = F[t];
}

// Causal conv via FFT: z = k_norm + i*v_norm per channel, 2 FFTs per channel.
// Filter spectrum F_c(t) reconstructed on the fly from the packed pair spectrum.
__global__ void fftconv_kernel() {
    extern __shared__ float2 smf[];
    float2* Z  = smf;              // 4096
    float2* TW = smf + NFFT;       // 2048
    int c = blockIdx.x, tid = threadIdx.x;  // 512 threads, 512 blocks
    make_tw(TW);
    for (int i = tid; i < NFFT; i += 512) {
        int r = __brev(i) >> 20;
        float kr = 0.f, vi = 0.f;
        if (r < LSEQ) { kr = g_k[r * DMODEL + c]; vi = g_v[r * DMODEL + c]; }
        Z[i] = make_float2(kr, vi);
    }
    fft12(Z, TW);
    const float2* Gp = g_Ff + (size_t)(c >> 1) * NFFT;
    int par = c & 1;
    float2 y[8];
#pragma unroll
    for (int jj = 0; jj < 8; jj++) {
        int t = tid + jj * 512;
        float2 Gt = Gp[t];
        float2 Gr = Gp[(NFFT - t) & (NFFT - 1)];
        // A(t) = (G + conj(Grev))/2 : spectrum of even channel (real input)
        // B(t) = (G - conj(Grev))/(2i): spectrum of odd channel
        float Ax = 0.5f * (Gt.x + Gr.x), Ay = 0.5f * (Gt.y - Gr.y);
        float Dx = 0.5f * (Gt.x - Gr.x), Dy = 0.5f * (Gt.y + Gr.y);
        float Fx = par ? Dy : Ax;
        float Fy = par ? -Dx : Ay;
        float2 z = Z[t];
        float pr = z.x * Fx - z.y * Fy;
        float pi = z.x * Fy + z.y * Fx;
        y[jj] = make_float2(pr, -pi);   // conj for IFFT-via-FFT
    }
    __syncthreads();
#pragma unroll
    for (int jj = 0; jj < 8; jj++) {
        int i = tid + jj * 512;
        Z[__brev(i) >> 20] = y[jj];
    }
    fft12(Z, TW);
    const float invN = 1.f / (float)NFFT;
    for (int t = tid; t < LSEQ; t += 512) {
        float2 w = Z[t];
        g_kf[t * DMODEL + c] =  w.x * invN;   // Re(conj) = Re
        g_vf[t * DMODEL + c] = -w.y * invN;   // Im(conj) = -Im
    }
}

// ---------------- gates: g_l = relu(v_f^T (W .* scale) k_f + b)^2 + eps ----------------
__global__ void gates_kernel(const float* __restrict__ wgz_w, const float* __restrict__ wgz_b,
                             const float* __restrict__ scale) {
    __shared__ float Wsc[HD * HD];
    int tid = threadIdx.x;  // 256
    for (int i = tid; i < HD * HD; i += blockDim.x) Wsc[i] = wgz_w[i] * scale[i];
    __syncthreads();
    int w = tid >> 5, lane = tid & 31;
    int p = blockIdx.x * 8 + w;           // p = h*2048 + l
    int h = p >> 11, l = p & (LSEQ - 1);
    const float* vrow = g_vf + l * DMODEL + h * HD;
    const float* krow = g_kf + l * DMODEL + h * HD;
    float acc = 0.f;
#pragma unroll
    for (int eo = 0; eo < 2; eo++) {
        int e = lane + eo * 32;
        float inner = 0.f;
#pragma unroll 16
        for (int d = 0; d < 64; d++) inner += vrow[d] * Wsc[d * 64 + e];
        acc += krow[e] * inner;
    }
#pragma unroll
    for (int o = 16; o; o >>= 1) acc += __shfl_xor_sync(0xffffffffu, acc, o);
    if (lane == 0) {
        float lg = acc + wgz_b[0];
        float r = fmaxf(lg, 0.f);
        g_gate[p] = r * r + EPSF;
    }
}

// ---------------- per-chunk rank-1 sums: S_c[d,e] = sum_{l in chunk} g_l v_f[l,d] k_f[l,e] ----
__global__ void chunksum_kernel() {
    int hb = blockIdx.x;                  // h*16 + c
    int h = hb >> 4, c = hb & 15;
    int tid = threadIdx.x;                // 128
    int e = tid >> 1, half = tid & 1, d0 = half * 32;
    float acc[32];
#pragma unroll
    for (int j = 0; j < 32; j++) acc[j] = 0.f;
    int l0 = c * TCH;
    for (int i = 0; i < TCH; i++) {
        int l = l0 + i;
        float gg = g_gate[h * LSEQ + l];
        float ke = g_kf[l * DMODEL + h * HD + e];
        float gk = gg * ke;
        const float4* vp = reinterpret_cast<const float4*>(g_vf + l * DMODEL + h * HD + d0);
#pragma unroll
        for (int j4 = 0; j4 < 8; j4++) {
            float4 v4 = vp[j4];
            acc[j4 * 4 + 0] += gk * v4.x;
            acc[j4 * 4 + 1] += gk * v4.y;
            acc[j4 * 4 + 2] += gk * v4.z;
            acc[j4 * 4 + 3] += gk * v4.w;
        }
    }
    float* Sp = g_S + (size_t)hb * HD * HD;
#pragma unroll
    for (int j = 0; j < 32; j++) Sp[(d0 + j) * 64 + e] = acc[j];
}

// ---------------- exclusive prefix over chunks (state matrices + gate sums) ----------------
__global__ void prefix_kernel() {
    int h = blockIdx.x, tid = threadIdx.x;  // 512
    __shared__ float gc[NCHUNK];
    if (tid < NCHUNK) {
        float s = 0.f;
        for (int i = 0; i < TCH; i++) s += g_gate[h * LSEQ + tid * TCH + i];
        gc[tid] = s;
    }
    __syncthreads();
    if (tid == 0) {
        float run = 0.f;
        for (int c = 0; c < NCHUNK; c++) { float t = gc[c]; g_Gpre[h * NCHUNK + c] = run; run += t; }
    }
    for (int idx = tid; idx < HD * HD; idx += 512) {
        float run = 0.f;
#pragma unroll
        for (int c = 0; c < NCHUNK; c++) {
            size_t off = ((size_t)(h * NCHUNK + c)) * HD * HD + idx;
            float t = g_S[off];
            g_Spre[off] = run;
            run += t;
        }
    }
}

// ---------------- intra-chunk scan + readout (256 threads: 4 threads per column e) -------
__global__ void scan_readout_kernel(const float* __restrict__ scale) {
    extern __shared__ float sm[];
    float* qs = sm;                // 128*64
    float* ks = sm + 8192;
    float* vs = sm + 16384;
    float* gs = sm + 24576;        // 128
    int hb = blockIdx.x;
    int h = hb >> 4, c = hb & 15;
    int tid = threadIdx.x;         // 256
    int l0 = c * TCH;
    for (int idx = tid; idx < TCH * HD; idx += 256) {
        int row = idx >> 6, col = idx & 63;
        int ga = (l0 + row) * DMODEL + h * HD + col;
        qs[idx] = g_q[ga];
        ks[idx] = g_kf[ga];
        vs[idx] = g_vf[ga];
    }
    if (tid < TCH) gs[tid] = g_gate[h * LSEQ + l0 + tid];
    int e = tid >> 2, quarter = tid & 3, d0 = quarter * 16;
    float M[16], sc[16];
    {
        const float* Sp = g_Spre + (size_t)hb * HD * HD;
#pragma unroll
        for (int j = 0; j < 16; j++) {
            M[j]  = Sp[(d0 + j) * 64 + e];
            sc[j] = scale[(d0 + j) * 64 + e];
        }
    }
    float G = g_Gpre[h * NCHUNK + c];
    __syncthreads();
    const float4* q4 = reinterpret_cast<const float4*>(qs);
    const float4* v4 = reinterpret_cast<const float4*>(vs);
    int o4 = quarter * 4;
    for (int i = 0; i < TCH; i++) {
        float gg = gs[i]; G += gg;
        float ke = ks[i * HD + e];
        float gk = gg * ke;
        float r = 0.f;
#pragma unroll
        for (int j4 = 0; j4 < 4; j4++) {
            float4 vv = v4[i * 16 + o4 + j4];
            float4 qq = q4[i * 16 + o4 + j4];
            int jb = j4 * 4;
            M[jb + 0] += gk * vv.x; r += qq.x * (sc[jb + 0] * M[jb + 0]);
            M[jb + 1] += gk * vv.y; r += qq.y * (sc[jb + 1] * M[jb + 1]);
            M[jb + 2] += gk * vv.z; r += qq.z * (sc[jb + 2] * M[jb + 2]);
            M[jb + 3] += gk * vv.w; r += qq.w * (sc[jb + 3] * M[jb + 3]);
        }
        r += __shfl_xor_sync(0xffffffffu, r, 1);
        r += __shfl_xor_sync(0xffffffffu, r, 2);
        if (quarter == 0) g_sraw[(l0 + i) * DMODEL + h * HD + e] = r / fmaxf(G, EPSF);
    }
}

// ---------------- l2-normalize sp per (l, head), in place ----------------
__global__ void spnorm_kernel() {
    int tid = threadIdx.x;          // 256
    int w = tid >> 5, lane = tid & 31;
    int p = blockIdx.x * 8 + w;     // l*8 + h
    int l = p >> 3, h = p & 7;
    float* base = g_sraw + l * DMODEL + h * HD;
    float a = base[lane], b = base[lane + 32];
    float ss = a * a + b * b;
#pragma unroll
    for (int o = 16; o; o >>= 1) ss += __shfl_xor_sync(0xffffffffu, ss, o);
    float inv = 1.f / fmaxf(sqrtf(ss), EPSF);
    base[lane] = a * inv;
    base[lane + 32] = b * inv;
}

// ---------------- launch ----------------
extern "C" void kernel_launch(void* const* d_in, const int* in_sizes, int n_in,
                              void* d_out, int out_size) {
    const float* x     = (const float*)d_in[0];
    const float* sb    = (const float*)d_in[1];
    const float* wq_w  = (const float*)d_in[2];
    const float* wq_b  = (const float*)d_in[3];
    const float* wk_w  = (const float*)d_in[4];
    const float* wk_b  = (const float*)d_in[5];
    const float* wv_w  = (const float*)d_in[6];
    const float* wv_b  = (const float*)d_in[7];
    const float* wo_w  = (const float*)d_in[8];
    const float* wo_b  = (const float*)d_in[9];
    const float* td_w  = (const float*)d_in[10];
    const float* td_b  = (const float*)d_in[11];
    const float* wgz_w = (const float*)d_in[12];
    const float* wgz_b = (const float*)d_in[13];
    const float* kvs   = (const float*)d_in[14];
    float* out = (float*)d_out;

    float* sp;
    cudaGetSymbolAddress((void**)&sp, g_sraw);

    cudaFuncSetAttribute(filtfft_kernel, cudaFuncAttributeMaxDynamicSharedMemorySize, 49152);
    cudaFuncSetAttribute(fftconv_kernel, cudaFuncAttributeMaxDynamicSharedMemorySize, 49152);
    cudaFuncSetAttribute(scan_readout_kernel, cudaFuncAttributeMaxDynamicSharedMemorySize, 98816);

    dim3 g4(DMODEL / 64, LSEQ / 64, 4);
    gemm4_kernel<<<g4, 256>>>(x, sb, wq_w, wk_w, wv_w, td_w, wq_b, wk_b, wv_b, td_b);
    l2norm_kv_kernel<<<LSEQ, 512>>>();
    filtfft_kernel<<<DMODEL / 2, 512, 49152>>>();
    fftconv_kernel<<<DMODEL, 512, 49152>>>();
    gates_kernel<<<(NH * LSEQ) / 8, 256>>>(wgz_w, wgz_b, kvs);
    chunksum_kernel<<<NH * NCHUNK, 128>>>();
    prefix_kernel<<<NH, 512>>>();
    scan_readout_kernel<<<NH * NCHUNK, 256, 98816>>>(kvs);
    spnorm_kernel<<<(LSEQ * NH) / 8, 256>>>();
    dim3 g1(DMODEL / 64, LSEQ / 64, 1);
    gemm1_kernel<<<g1, 256>>>(sp, wo_w, wo_b, out);
}

// round 6
// speedup vs baseline: 1.2936x; 1.1694x over previous
#include <cuda_runtime.h>
#include <math.h>

#define LSEQ 2048
#define DMODEL 512
#define NH 8
#define HD 64
#define NFFT 4096
#define EPSF 1e-5f
#define NCHUNK 16
#define TCH 128

typedef unsigned long long u64;

// ---------------- scratch (device globals; no runtime allocation) ----------------
__device__ float g_q[LSEQ * DMODEL];
__device__ float g_k[LSEQ * DMODEL];
__device__ float g_v[LSEQ * DMODEL];
__device__ float g_filt[LSEQ * DMODEL];
__device__ float g_kf[LSEQ * DMODEL];
__device__ float g_vf[LSEQ * DMODEL];
__device__ float g_gate[NH * LSEQ];
__device__ float g_S[NH * NCHUNK * HD * HD];
__device__ float g_Spre[NH * NCHUNK * HD * HD];
__device__ float g_Gpre[NH * NCHUNK];
__device__ float g_sraw[LSEQ * DMODEL];
__device__ float2 g_Ff[(DMODEL / 2) * NFFT];   // packed filter spectra (2 channels/FFT)

// ---------------- packed f32x2 helpers (sm_103a FFMA2 path) ----------------
__device__ __forceinline__ u64 pk2(float v) {
    u64 r; asm("mov.b64 %0, {%1, %1};" : "=l"(r) : "f"(v)); return r;
}
__device__ __forceinline__ void upk2(u64 v, float& lo, float& hi) {
    asm("mov.b64 {%0, %1}, %2;" : "=f"(lo), "=f"(hi) : "l"(v));
}
__device__ __forceinline__ u64 ffma2(u64 a, u64 b, u64 c) {
    u64 d; asm("fma.rn.f32x2 %0, %1, %2, %3;" : "=l"(d) : "l"(a), "l"(b), "l"(c)); return d;
}

// ---------------- double-buffered GEMM body: C[m,n] = sum_k A[m,k]*W[n,k] + bias[n] -------
// 64x64 tile, 256 threads, 4x4 acc (packed f32x2), K=N=512 fixed.
__device__ __forceinline__ void gemm_body(const float* __restrict__ A, const float* __restrict__ W,
                                          const float* __restrict__ bias, float* __restrict__ C) {
    __shared__ __align__(16) float As[2][16][68];
    __shared__ __align__(16) float Ws[2][16][68];
    int tid = threadIdx.x;                 // 256 threads
    int bm = blockIdx.y * 64, bn = blockIdx.x * 64;
    int row = tid >> 2, kc = (tid & 3) << 2;
    int tx = tid & 15, ty = tid >> 4;
    const float* Ap = A + (size_t)(bm + row) * DMODEL + kc;
    const float* Wp = W + (size_t)(bn + row) * DMODEL + kc;

    u64 acc2[4][2];
#pragma unroll
    for (int i = 0; i < 4; i++) { acc2[i][0] = 0ull; acc2[i][1] = 0ull; }

    // preload tile 0
    {
        float4 a4 = *reinterpret_cast<const float4*>(Ap);
        float4 w4 = *reinterpret_cast<const float4*>(Wp);
        As[0][kc + 0][row] = a4.x; As[0][kc + 1][row] = a4.y; As[0][kc + 2][row] = a4.z; As[0][kc + 3][row] = a4.w;
        Ws[0][kc + 0][row] = w4.x; Ws[0][kc + 1][row] = w4.y; Ws[0][kc + 2][row] = w4.z; Ws[0][kc + 3][row] = w4.w;
    }
    __syncthreads();

    int buf = 0;
    for (int k0 = 16; k0 <= DMODEL; k0 += 16) {
        float4 a4n, w4n;
        bool more = (k0 < DMODEL);
        if (more) {
            a4n = *reinterpret_cast<const float4*>(Ap + k0);
            w4n = *reinterpret_cast<const float4*>(Wp + k0);
        }
#pragma unroll
        for (int kk = 0; kk < 16; kk++) {
            const u64* bp = reinterpret_cast<const u64*>(&Ws[buf][kk][tx * 4]);
            u64 b0 = bp[0], b1 = bp[1];
#pragma unroll
            for (int i = 0; i < 4; i++) {
                u64 ap = pk2(As[buf][kk][ty * 4 + i]);
                acc2[i][0] = ffma2(ap, b0, acc2[i][0]);
                acc2[i][1] = ffma2(ap, b1, acc2[i][1]);
            }
        }
        if (more) {
            int nb = buf ^ 1;
            As[nb][kc + 0][row] = a4n.x; As[nb][kc + 1][row] = a4n.y; As[nb][kc + 2][row] = a4n.z; As[nb][kc + 3][row] = a4n.w;
            Ws[nb][kc + 0][row] = w4n.x; Ws[nb][kc + 1][row] = w4n.y; Ws[nb][kc + 2][row] = w4n.z; Ws[nb][kc + 3][row] = w4n.w;
            __syncthreads();
        }
        buf ^= 1;
    }
    float4 bb = *reinterpret_cast<const float4*>(bias + bn + tx * 4);
#pragma unroll
    for (int i = 0; i < 4; i++) {
        float c0, c1, c2, c3;
        upk2(acc2[i][0], c0, c1);
        upk2(acc2[i][1], c2, c3);
        float4 c4 = make_float4(c0 + bb.x, c1 + bb.y, c2 + bb.z, c3 + bb.w);
        *reinterpret_cast<float4*>(C + (size_t)(bm + ty * 4 + i) * DMODEL + bn + tx * 4) = c4;
    }
}

// fused Q/K/V/filter projections: blockIdx.z selects the GEMM (1024 blocks total)
__global__ __launch_bounds__(256) void gemm4_kernel(
    const float* __restrict__ x, const float* __restrict__ sb,
    const float* __restrict__ Wq, const float* __restrict__ Wk,
    const float* __restrict__ Wv, const float* __restrict__ Wt,
    const float* __restrict__ bq, const float* __restrict__ bk,
    const float* __restrict__ bv, const float* __restrict__ bt) {
    int z = blockIdx.z;
    const float* A = (z == 3) ? sb : x;
    const float* W = (z == 0) ? Wq : (z == 1) ? Wk : (z == 2) ? Wv : Wt;
    const float* b = (z == 0) ? bq : (z == 1) ? bk : (z == 2) ? bv : bt;
    float* C = (z == 0) ? g_q : (z == 1) ? g_k : (z == 2) ? g_v : g_filt;
    gemm_body(A, W, b, C);
}

__global__ __launch_bounds__(256) void gemm1_kernel(const float* __restrict__ A, const float* __restrict__ W,
                                                    const float* __restrict__ bias, float* __restrict__ C) {
    gemm_body(A, W, bias, C);
}

// ---------------- per-(l,head) L2 norm of k and v, warp-shuffle version ----------------
__global__ void l2norm_kv_kernel() {
    int tid = threadIdx.x;          // 256
    int w = tid >> 5, lane = tid & 31;
    int p = blockIdx.x * 8 + w;     // p = l*8 + h, 16384 total
    int l = p >> 3, h = p & 7;
    float* kb = g_k + l * DMODEL + h * HD;
    float* vb = g_v + l * DMODEL + h * HD;
    float k0 = kb[lane], k1 = kb[lane + 32];
    float v0 = vb[lane], v1 = vb[lane + 32];
    float sk = k0 * k0 + k1 * k1;
    float sv = v0 * v0 + v1 * v1;
#pragma unroll
    for (int o = 16; o; o >>= 1) {
        sk += __shfl_xor_sync(0xffffffffu, sk, o);
        sv += __shfl_xor_sync(0xffffffffu, sv, o);
    }
    float ik = 1.f / fmaxf(sqrtf(sk), EPSF);
    float iv = 1.f / fmaxf(sqrtf(sv), EPSF);
    kb[lane] = k0 * ik; kb[lane + 32] = k1 * ik;
    vb[lane] = v0 * iv; vb[lane + 32] = v1 * iv;
}

// ---------------- radix-4 DIT FFT over 4096 complex points in smem (6 stages) ----------
__device__ __forceinline__ float2 cmul(float2 a, float2 b) {
    return make_float2(a.x * b.x - a.y * b.y, a.x * b.y + a.y * b.x);
}

// base-4 digit reversal of a 12-bit index
__device__ __forceinline__ int dr4(int i) {
    int r = __brev(i) >> 20;
    return ((r & 0x555) << 1) | ((r >> 1) & 0x555);
}

__device__ __forceinline__ void fft12r4(float2* A, const float2* TW) {
#pragma unroll
    for (int s = 0; s < 6; s++) {
        __syncthreads();
#pragma unroll
        for (int half = 0; half < 2; half++) {
            int j = threadIdx.x + half * 512;     // 1024 butterflies/stage
            int L = 1 << (2 * s);
            int p = j & (L - 1);
            int base = ((j >> (2 * s)) << (2 * s + 2)) + p;
            int sh = 10 - 2 * s;
            float2 a0 = A[base], a1 = A[base + L], a2 = A[base + 2 * L], a3 = A[base + 3 * L];
            float2 w1 = TW[p << sh];
            float2 w2 = TW[(p << sh) << 1];
            float2 w3 = cmul(w1, w2);
            float2 t1 = cmul(a1, w1);
            float2 t2 = cmul(a2, w2);
            float2 t3 = cmul(a3, w3);
            float u0x = a0.x + t2.x, u0y = a0.y + t2.y;
            float u1x = a0.x - t2.x, u1y = a0.y - t2.y;
            float u2x = t1.x + t3.x, u2y = t1.y + t3.y;
            float u3x = t1.x - t3.x, u3y = t1.y - t3.y;
            A[base]         = make_float2(u0x + u2x, u0y + u2y);
            A[base + L]     = make_float2(u1x + u3y, u1y - u3x);  // u1 - i*u3
            A[base + 2 * L] = make_float2(u0x - u2x, u0y - u2y);
            A[base + 3 * L] = make_float2(u1x - u3y, u1y + u3x);  // u1 + i*u3
        }
    }
    __syncthreads();
}

__device__ __forceinline__ void make_tw(float2* TW) {
    for (int t = threadIdx.x; t < NFFT / 2; t += 512) {
        float s, co;
        __sincosf(-6.283185307179586f * (float)t / (float)NFFT, &s, &co);
        TW[t] = make_float2(co, s);
    }
}

// Precompute filter spectra: one complex FFT per CHANNEL PAIR (f_{2p} + i f_{2p+1}).
__global__ void filtfft_kernel() {
    extern __shared__ float2 smf[];
    float2* F  = smf;              // 4096
    float2* TW = smf + NFFT;       // 2048
    int p = blockIdx.x, tid = threadIdx.x;  // 512 threads, 256 blocks
    int c0 = 2 * p;
    make_tw(TW);
    for (int i = tid; i < NFFT; i += 512) {
        int r = dr4(i);
        float v0 = 0.f, v1 = 0.f;
        if (r < LSEQ) { v0 = g_filt[r * DMODEL + c0]; v1 = g_filt[r * DMODEL + c0 + 1]; }
        F[i] = make_float2(v0, v1);
    }
    fft12r4(F, TW);
    float2* Gp = g_Ff + (size_t)p * NFFT;
    for (int t = tid; t < NFFT; t += 512) Gp[t] = F[t];
}

// Causal conv via FFT: z = k_norm + i*v_norm per channel; filter spectrum
// reconstructed on the fly from the packed pair spectrum (conjugate symmetry).
__global__ void fftconv_kernel() {
    extern __shared__ float2 smf[];
    float2* Z  = smf;              // 4096
    float2* TW = smf + NFFT;       // 2048
    int c = blockIdx.x, tid = threadIdx.x;  // 512 threads, 512 blocks
    make_tw(TW);
    for (int i = tid; i < NFFT; i += 512) {
        int r = dr4(i);
        float kr = 0.f, vi = 0.f;
        if (r < LSEQ) { kr = g_k[r * DMODEL + c]; vi = g_v[r * DMODEL + c]; }
        Z[i] = make_float2(kr, vi);
    }
    fft12r4(Z, TW);
    const float2* Gp = g_Ff + (size_t)(c >> 1) * NFFT;
    int par = c & 1;
    float2 y[8];
#pragma unroll
    for (int jj = 0; jj < 8; jj++) {
        int t = tid + jj * 512;
        float2 Gt = Gp[t];
        float2 Gr = Gp[(NFFT - t) & (NFFT - 1)];
        float Ax = 0.5f * (Gt.x + Gr.x), Ay = 0.5f * (Gt.y - Gr.y);
        float Dx = 0.5f * (Gt.x - Gr.x), Dy = 0.5f * (Gt.y + Gr.y);
        float Fx = par ? Dy : Ax;
        float Fy = par ? -Dx : Ay;
        float2 z = Z[t];
        float pr = z.x * Fx - z.y * Fy;
        float pi = z.x * Fy + z.y * Fx;
        y[jj] = make_float2(pr, -pi);   // conj for IFFT-via-FFT
    }
    __syncthreads();
#pragma unroll
    for (int jj = 0; jj < 8; jj++) {
        int i = tid + jj * 512;
        Z[dr4(i)] = y[jj];
    }
    fft12r4(Z, TW);
    const float invN = 1.f / (float)NFFT;
    for (int t = tid; t < LSEQ; t += 512) {
        float2 w = Z[t];
        g_kf[t * DMODEL + c] =  w.x * invN;   // Re(conj) = Re
        g_vf[t * DMODEL + c] = -w.y * invN;   // Im(conj) = -Im
    }
}

// ---------------- gates: g_l = relu(v_f^T (W .* scale) k_f + b)^2 + eps ----------------
__global__ void gates_kernel(const float* __restrict__ wgz_w, const float* __restrict__ wgz_b,
                             const float* __restrict__ scale) {
    __shared__ float Wsc[HD * HD];
    int tid = threadIdx.x;  // 256
    for (int i = tid; i < HD * HD; i += blockDim.x) Wsc[i] = wgz_w[i] * scale[i];
    __syncthreads();
    int w = tid >> 5, lane = tid & 31;
    int p = blockIdx.x * 8 + w;           // p = h*2048 + l
    int h = p >> 11, l = p & (LSEQ - 1);
    const float* vrow = g_vf + l * DMODEL + h * HD;
    const float* krow = g_kf + l * DMODEL + h * HD;
    float acc = 0.f;
#pragma unroll
    for (int eo = 0; eo < 2; eo++) {
        int e = lane + eo * 32;
        float inner = 0.f;
#pragma unroll 16
        for (int d = 0; d < 64; d++) inner += vrow[d] * Wsc[d * 64 + e];
        acc += krow[e] * inner;
    }
#pragma unroll
    for (int o = 16; o; o >>= 1) acc += __shfl_xor_sync(0xffffffffu, acc, o);
    if (lane == 0) {
        float lg = acc + wgz_b[0];
        float r = fmaxf(lg, 0.f);
        g_gate[p] = r * r + EPSF;
    }
}

// ---------------- per-chunk rank-1 sums: S_c[d,e] = sum_{l in chunk} g_l v_f[l,d] k_f[l,e] ----
__global__ void chunksum_kernel() {
    int hb = blockIdx.x;                  // h*16 + c
    int h = hb >> 4, c = hb & 15;
    int tid = threadIdx.x;                // 128
    int e = tid >> 1, half = tid & 1, d0 = half * 32;
    float acc[32];
#pragma unroll
    for (int j = 0; j < 32; j++) acc[j] = 0.f;
    int l0 = c * TCH;
    for (int i = 0; i < TCH; i++) {
        int l = l0 + i;
        float gg = g_gate[h * LSEQ + l];
        float ke = g_kf[l * DMODEL + h * HD + e];
        float gk = gg * ke;
        const float4* vp = reinterpret_cast<const float4*>(g_vf + l * DMODEL + h * HD + d0);
#pragma unroll
        for (int j4 = 0; j4 < 8; j4++) {
            float4 v4 = vp[j4];
            acc[j4 * 4 + 0] += gk * v4.x;
            acc[j4 * 4 + 1] += gk * v4.y;
            acc[j4 * 4 + 2] += gk * v4.z;
            acc[j4 * 4 + 3] += gk * v4.w;
        }
    }
    float* Sp = g_S + (size_t)hb * HD * HD;
#pragma unroll
    for (int j = 0; j < 32; j++) Sp[(d0 + j) * 64 + e] = acc[j];
}

// ---------------- exclusive prefix over chunks (state matrices + gate sums) ----------------
__global__ void prefix_kernel() {
    int h = blockIdx.x, tid = threadIdx.x;  // 512
    __shared__ float gc[NCHUNK];
    if (tid < NCHUNK) {
        float s = 0.f;
        for (int i = 0; i < TCH; i++) s += g_gate[h * LSEQ + tid * TCH + i];
        gc[tid] = s;
    }
    __syncthreads();
    if (tid == 0) {
        float run = 0.f;
        for (int c = 0; c < NCHUNK; c++) { float t = gc[c]; g_Gpre[h * NCHUNK + c] = run; run += t; }
    }
    for (int idx = tid; idx < HD * HD; idx += 512) {
        float run = 0.f;
#pragma unroll
        for (int c = 0; c < NCHUNK; c++) {
            size_t off = ((size_t)(h * NCHUNK + c)) * HD * HD + idx;
            float t = g_S[off];
            g_Spre[off] = run;
            run += t;
        }
    }
}

// ---------------- intra-chunk scan + readout (256 threads: 4 threads per column e) -------
__global__ void scan_readout_kernel(const float* __restrict__ scale) {
    extern __shared__ float sm[];
    float* qs = sm;                // 128*64
    float* ks = sm + 8192;
    float* vs = sm + 16384;
    float* gs = sm + 24576;        // 128
    int hb = blockIdx.x;
    int h = hb >> 4, c = hb & 15;
    int tid = threadIdx.x;         // 256
    int l0 = c * TCH;
    for (int idx = tid; idx < TCH * HD; idx += 256) {
        int row = idx >> 6, col = idx & 63;
        int ga = (l0 + row) * DMODEL + h * HD + col;
        qs[idx] = g_q[ga];
        ks[idx] = g_kf[ga];
        vs[idx] = g_vf[ga];
    }
    if (tid < TCH) gs[tid] = g_gate[h * LSEQ + l0 + tid];
    int e = tid >> 2, quarter = tid & 3, d0 = quarter * 16;
    float M[16], sc[16];
    {
        const float* Sp = g_Spre + (size_t)hb * HD * HD;
#pragma unroll
        for (int j = 0; j < 16; j++) {
            M[j]  = Sp[(d0 + j) * 64 + e];
            sc[j] = scale[(d0 + j) * 64 + e];
        }
    }
    float G = g_Gpre[h * NCHUNK + c];
    __syncthreads();
    const float4* q4 = reinterpret_cast<const float4*>(qs);
    const float4* v4 = reinterpret_cast<const float4*>(vs);
    int o4 = quarter * 4;
    for (int i = 0; i < TCH; i++) {
        float gg = gs[i]; G += gg;
        float ke = ks[i * HD + e];
        float gk = gg * ke;
        float r = 0.f;
#pragma unroll
        for (int j4 = 0; j4 < 4; j4++) {
            float4 vv = v4[i * 16 + o4 + j4];
            float4 qq = q4[i * 16 + o4 + j4];
            int jb = j4 * 4;
            M[jb + 0] += gk * vv.x; r += qq.x * (sc[jb + 0] * M[jb + 0]);
            M[jb + 1] += gk * vv.y; r += qq.y * (sc[jb + 1] * M[jb + 1]);
            M[jb + 2] += gk * vv.z; r += qq.z * (sc[jb + 2] * M[jb + 2]);
            M[jb + 3] += gk * vv.w; r += qq.w * (sc[jb + 3] * M[jb + 3]);
        }
        r += __shfl_xor_sync(0xffffffffu, r, 1);
        r += __shfl_xor_sync(0xffffffffu, r, 2);
        if (quarter == 0) g_sraw[(l0 + i) * DMODEL + h * HD + e] = r / fmaxf(G, EPSF);
    }
}

// ---------------- l2-normalize sp per (l, head), in place ----------------
__global__ void spnorm_kernel() {
    int tid = threadIdx.x;          // 256
    int w = tid >> 5, lane = tid & 31;
    int p = blockIdx.x * 8 + w;     // l*8 + h
    int l = p >> 3, h = p & 7;
    float* base = g_sraw + l * DMODEL + h * HD;
    float a = base[lane], b = base[lane + 32];
    float ss = a * a + b * b;
#pragma unroll
    for (int o = 16; o; o >>= 1) ss += __shfl_xor_sync(0xffffffffu, ss, o);
    float inv = 1.f / fmaxf(sqrtf(ss), EPSF);
    base[lane] = a * inv;
    base[lane + 32] = b * inv;
}

// ---------------- launch ----------------
extern "C" void kernel_launch(void* const* d_in, const int* in_sizes, int n_in,
                              void* d_out, int out_size) {
    const float* x     = (const float*)d_in[0];
    const float* sb    = (const float*)d_in[1];
    const float* wq_w  = (const float*)d_in[2];
    const float* wq_b  = (const float*)d_in[3];
    const float* wk_w  = (const float*)d_in[4];
    const float* wk_b  = (const float*)d_in[5];
    const float* wv_w  = (const float*)d_in[6];
    const float* wv_b  = (const float*)d_in[7];
    const float* wo_w  = (const float*)d_in[8];
    const float* wo_b  = (const float*)d_in[9];
    const float* td_w  = (const float*)d_in[10];
    const float* td_b  = (const float*)d_in[11];
    const float* wgz_w = (const float*)d_in[12];
    const float* wgz_b = (const float*)d_in[13];
    const float* kvs   = (const float*)d_in[14];
    float* out = (float*)d_out;

    float* sp;
    cudaGetSymbolAddress((void**)&sp, g_sraw);

    cudaFuncSetAttribute(filtfft_kernel, cudaFuncAttributeMaxDynamicSharedMemorySize, 49152);
    cudaFuncSetAttribute(fftconv_kernel, cudaFuncAttributeMaxDynamicSharedMemorySize, 49152);
    cudaFuncSetAttribute(scan_readout_kernel, cudaFuncAttributeMaxDynamicSharedMemorySize, 98816);

    dim3 g4(DMODEL / 64, LSEQ / 64, 4);
    gemm4_kernel<<<g4, 256>>>(x, sb, wq_w, wk_w, wv_w, td_w, wq_b, wk_b, wv_b, td_b);
    l2norm_kv_kernel<<<(LSEQ * NH) / 8, 256>>>();
    filtfft_kernel<<<DMODEL / 2, 512, 49152>>>();
    fftconv_kernel<<<DMODEL, 512, 49152>>>();
    gates_kernel<<<(NH * LSEQ) / 8, 256>>>(wgz_w, wgz_b, kvs);
    chunksum_kernel<<<NH * NCHUNK, 128>>>();
    prefix_kernel<<<NH, 512>>>();
    scan_readout_kernel<<<NH * NCHUNK, 256, 98816>>>(kvs);
    spnorm_kernel<<<(LSEQ * NH) / 8, 256>>>();
    dim3 g1(DMODEL / 64, LSEQ / 64, 1);
    gemm1_kernel<<<g1, 256>>>(sp, wo_w, wo_b, out);
}

// round 8
// speedup vs baseline: 1.3853x; 1.0710x over previous
#include <cuda_runtime.h>
#include <math.h>

#define LSEQ 2048
#define DMODEL 512
#define NH 8
#define HD 64
#define NFFT 4096
#define EPSF 1e-5f
#define NCHUNK 16
#define TCH 128

typedef unsigned long long u64;

// ---------------- scratch (device globals; no runtime allocation) ----------------
__device__ float g_q[LSEQ * DMODEL];
__device__ float g_k[LSEQ * DMODEL];
__device__ float g_v[LSEQ * DMODEL];
__device__ float g_filt[LSEQ * DMODEL];
__device__ float g_kf[LSEQ * DMODEL];
__device__ float g_vf[LSEQ * DMODEL];
__device__ float g_gate[NH * LSEQ];
__device__ float g_S[NH * NCHUNK * HD * HD];
__device__ float g_Spre[NH * NCHUNK * HD * HD];
__device__ float g_Gpre[NH * NCHUNK];
__device__ float g_sraw[LSEQ * DMODEL];
__device__ float2 g_Ff[(DMODEL / 2) * NFFT];   // packed filter spectra (2 channels/FFT)

// ---------------- packed f32x2 helpers (sm_103a FFMA2 path) ----------------
__device__ __forceinline__ u64 pk2(float v) {
    u64 r; asm("mov.b64 %0, {%1, %1};" : "=l"(r) : "f"(v)); return r;
}
__device__ __forceinline__ void upk2(u64 v, float& lo, float& hi) {
    asm("mov.b64 {%0, %1}, %2;" : "=f"(lo), "=f"(hi) : "l"(v));
}
__device__ __forceinline__ u64 ffma2(u64 a, u64 b, u64 c) {
    u64 d; asm("fma.rn.f32x2 %0, %1, %2, %3;" : "=l"(d) : "l"(a), "l"(b), "l"(c)); return d;
}

// ---------------- double-buffered GEMM body: C[m,n] = sum_k A[m,k]*W[n,k] + bias[n] -------
// 64x64 tile, 256 threads, 4x4 acc (packed f32x2), K=N=512 fixed.
// l2n != 0: L2-normalize each 64-wide output row segment (N-tile == one head).
__device__ __forceinline__ void gemm_body(const float* __restrict__ A, const float* __restrict__ W,
                                          const float* __restrict__ bias, float* __restrict__ C,
                                          int l2n) {
    __shared__ __align__(16) float As[2][16][68];
    __shared__ __align__(16) float Ws[2][16][68];
    int tid = threadIdx.x;                 // 256 threads
    int bm = blockIdx.y * 64, bn = blockIdx.x * 64;
    int row = tid >> 2, kc = (tid & 3) << 2;
    int tx = tid & 15, ty = tid >> 4;
    const float* Ap = A + (size_t)(bm + row) * DMODEL + kc;
    const float* Wp = W + (size_t)(bn + row) * DMODEL + kc;

    u64 acc2[4][2];
#pragma unroll
    for (int i = 0; i < 4; i++) { acc2[i][0] = 0ull; acc2[i][1] = 0ull; }

    // preload tile 0
    {
        float4 a4 = *reinterpret_cast<const float4*>(Ap);
        float4 w4 = *reinterpret_cast<const float4*>(Wp);
        As[0][kc + 0][row] = a4.x; As[0][kc + 1][row] = a4.y; As[0][kc + 2][row] = a4.z; As[0][kc + 3][row] = a4.w;
        Ws[0][kc + 0][row] = w4.x; Ws[0][kc + 1][row] = w4.y; Ws[0][kc + 2][row] = w4.z; Ws[0][kc + 3][row] = w4.w;
    }
    __syncthreads();

    int buf = 0;
    for (int k0 = 16; k0 <= DMODEL; k0 += 16) {
        float4 a4n, w4n;
        bool more = (k0 < DMODEL);
        if (more) {
            a4n = *reinterpret_cast<const float4*>(Ap + k0);
            w4n = *reinterpret_cast<const float4*>(Wp + k0);
        }
#pragma unroll
        for (int kk = 0; kk < 16; kk++) {
            const u64* bp = reinterpret_cast<const u64*>(&Ws[buf][kk][tx * 4]);
            u64 b0 = bp[0], b1 = bp[1];
#pragma unroll
            for (int i = 0; i < 4; i++) {
                u64 ap = pk2(As[buf][kk][ty * 4 + i]);
                acc2[i][0] = ffma2(ap, b0, acc2[i][0]);
                acc2[i][1] = ffma2(ap, b1, acc2[i][1]);
            }
        }
        if (more) {
            int nb = buf ^ 1;
            As[nb][kc + 0][row] = a4n.x; As[nb][kc + 1][row] = a4n.y; As[nb][kc + 2][row] = a4n.z; As[nb][kc + 3][row] = a4n.w;
            Ws[nb][kc + 0][row] = w4n.x; Ws[nb][kc + 1][row] = w4n.y; Ws[nb][kc + 2][row] = w4n.z; Ws[nb][kc + 3][row] = w4n.w;
            __syncthreads();
        }
        buf ^= 1;
    }
    float4 bb = *reinterpret_cast<const float4*>(bias + bn + tx * 4);
#pragma unroll
    for (int i = 0; i < 4; i++) {
        float c0, c1, c2, c3;
        upk2(acc2[i][0], c0, c1);
        upk2(acc2[i][1], c2, c3);
        c0 += bb.x; c1 += bb.y; c2 += bb.z; c3 += bb.w;
        if (l2n) {
            // row (bm+ty*4+i) spans exactly one head; its 64 values live in the
            // 16-lane half-warp group {lane & ~15 .. | 15} (tx = lane & 15).
            float ss = c0 * c0 + c1 * c1 + c2 * c2 + c3 * c3;
            ss += __shfl_xor_sync(0xffffffffu, ss, 1);
            ss += __shfl_xor_sync(0xffffffffu, ss, 2);
            ss += __shfl_xor_sync(0xffffffffu, ss, 4);
            ss += __shfl_xor_sync(0xffffffffu, ss, 8);
            float inv = 1.f / fmaxf(sqrtf(ss), EPSF);
            c0 *= inv; c1 *= inv; c2 *= inv; c3 *= inv;
        }
        *reinterpret_cast<float4*>(C + (size_t)(bm + ty * 4 + i) * DMODEL + bn + tx * 4)
            = make_float4(c0, c1, c2, c3);
    }
}

// fused Q/K/V/filter projections: blockIdx.z selects the GEMM (1024 blocks total)
__global__ __launch_bounds__(256) void gemm4_kernel(
    const float* __restrict__ x, const float* __restrict__ sb,
    const float* __restrict__ Wq, const float* __restrict__ Wk,
    const float* __restrict__ Wv, const float* __restrict__ Wt,
    const float* __restrict__ bq, const float* __restrict__ bk,
    const float* __restrict__ bv, const float* __restrict__ bt) {
    int z = blockIdx.z;
    const float* A = (z == 3) ? sb : x;
    const float* W = (z == 0) ? Wq : (z == 1) ? Wk : (z == 2) ? Wv : Wt;
    const float* b = (z == 0) ? bq : (z == 1) ? bk : (z == 2) ? bv : bt;
    float* C = (z == 0) ? g_q : (z == 1) ? g_k : (z == 2) ? g_v : g_filt;
    gemm_body(A, W, b, C, (z == 1 || z == 2) ? 1 : 0);
}

__global__ __launch_bounds__(256) void gemm1_kernel(const float* __restrict__ A, const float* __restrict__ W,
                                                    const float* __restrict__ bias, float* __restrict__ C) {
    gemm_body(A, W, bias, C, 0);
}

// ---------------- FFT over 4096 complex points: 3 register-resident radix-16 super-stages
// Additive bank swizzle for smem data + twiddles (verified <=4-way on all patterns).
#define IDX(i) ((i) + ((i) >> 5))
#define A_ELEMS (NFFT + NFFT / 32)                 // 4224 float2
#define TW_ELEMS (NFFT / 2 + NFFT / 64)            // 2112 float2
#define FFT_SMEM ((A_ELEMS + TW_ELEMS) * 8)        // 50688 bytes

__device__ __forceinline__ float2 cmul(float2 a, float2 b) {
    return make_float2(a.x * b.x - a.y * b.y, a.x * b.y + a.y * b.x);
}

// base-4 digit reversal of a 12-bit index
__device__ __forceinline__ int dr4(int i) {
    int r = __brev(i) >> 20;
    return ((r & 0x555) << 1) | ((r >> 1) & 0x555);
}

__device__ __forceinline__ void bfly4(float2& a0, float2& a1, float2& a2, float2& a3,
                                      float2 w1, float2 w2, float2 w3) {
    float2 t1 = cmul(a1, w1);
    float2 t2 = cmul(a2, w2);
    float2 t3 = cmul(a3, w3);
    float u0x = a0.x + t2.x, u0y = a0.y + t2.y;
    float u1x = a0.x - t2.x, u1y = a0.y - t2.y;
    float u2x = t1.x + t3.x, u2y = t1.y + t3.y;
    float u3x = t1.x - t3.x, u3y = t1.y - t3.y;
    a0 = make_float2(u0x + u2x, u0y + u2y);
    a1 = make_float2(u1x + u3y, u1y - u3x);   // u1 - i*u3
    a2 = make_float2(u0x - u2x, u0y - u2y);
    a3 = make_float2(u1x - u3y, u1y + u3x);   // u1 + i*u3
}

// 256 threads; identical butterfly network to the 6-stage radix-4 version,
// with stage pairs (0,1),(2,3),(4,5) fused in registers.
__device__ __forceinline__ void fft4096_r16(float2* A, const float2* TW) {
    int g = threadIdx.x;   // 256 groups of 16 points
#pragma unroll
    for (int t = 0; t < 3; t++) {
        __syncthreads();
        const int fourt = 4 * t;
        const int L = 1 << fourt;
        const int p = g & (L - 1);
        const int base = ((g >> fourt) << (fourt + 4)) + p;
        const int sh = 10 - fourt;
        float2 x[16];
#pragma unroll
        for (int q = 0; q < 16; q++) x[q] = A[IDX(base + (q << fourt))];
        {   // stage 2t: same twiddles for all 4 sub-butterflies
            float2 w1 = TW[IDX(p << sh)];
            float2 w2 = TW[IDX((p << sh) << 1)];
            float2 w3 = cmul(w1, w2);
#pragma unroll
            for (int r = 0; r < 4; r++)
                bfly4(x[4 * r], x[4 * r + 1], x[4 * r + 2], x[4 * r + 3], w1, w2, w3);
        }
        // stage 2t+1: stride 4L within the 16-point set
#pragma unroll
        for (int q0 = 0; q0 < 4; q0++) {
            int idx = (p + (q0 << fourt)) << (sh - 2);
            float2 w1 = TW[IDX(idx)];
            float2 w2 = TW[IDX(idx << 1)];
            float2 w3 = cmul(w1, w2);
            bfly4(x[q0], x[q0 + 4], x[q0 + 8], x[q0 + 12], w1, w2, w3);
        }
#pragma unroll
        for (int q = 0; q < 16; q++) A[IDX(base + (q << fourt))] = x[q];
    }
    __syncthreads();
}

__device__ __forceinline__ void make_tw(float2* TW) {
    for (int t = threadIdx.x; t < NFFT / 2; t += 256) {
        float s, co;
        __sincosf(-6.283185307179586f * (float)t / (float)NFFT, &s, &co);
        TW[IDX(t)] = make_float2(co, s);
    }
}

// Precompute filter spectra: one complex FFT per CHANNEL PAIR (f_{2p} + i f_{2p+1}).
__global__ __launch_bounds__(256) void filtfft_kernel() {
    extern __shared__ float2 smf[];
    float2* F  = smf;                 // swizzled, 4224
    float2* TW = smf + A_ELEMS;       // swizzled, 2112
    int pb = blockIdx.x, tid = threadIdx.x;  // 256 threads, 256 blocks
    int c0 = 2 * pb;
    make_tw(TW);
    __syncthreads();
    for (int i = tid; i < NFFT; i += 256) {
        int r = dr4(i);
        float v0 = 0.f, v1 = 0.f;
        if (r < LSEQ) { v0 = g_filt[r * DMODEL + c0]; v1 = g_filt[r * DMODEL + c0 + 1]; }
        F[IDX(i)] = make_float2(v0, v1);
    }
    fft4096_r16(F, TW);
    float2* Gp = g_Ff + (size_t)pb * NFFT;
    for (int t = tid; t < NFFT; t += 256) Gp[t] = F[IDX(t)];
}

// Causal conv via FFT: z = k_norm + i*v_norm per channel; filter spectrum
// reconstructed on the fly from the packed pair spectrum (conjugate symmetry).
__global__ __launch_bounds__(256) void fftconv_kernel() {
    extern __shared__ float2 smf[];
    float2* Z  = smf;                 // swizzled, 4224
    float2* TW = smf + A_ELEMS;       // swizzled, 2112
    int c = blockIdx.x, tid = threadIdx.x;  // 256 threads, 512 blocks
    make_tw(TW);
    __syncthreads();
    for (int i = tid; i < NFFT; i += 256) {
        int r = dr4(i);
        float kr = 0.f, vi = 0.f;
        if (r < LSEQ) { kr = g_k[r * DMODEL + c]; vi = g_v[r * DMODEL + c]; }
        Z[IDX(i)] = make_float2(kr, vi);
    }
    fft4096_r16(Z, TW);
    const float2* Gp = g_Ff + (size_t)(c >> 1) * NFFT;
    int par = c & 1;
    float2 y[16];
#pragma unroll
    for (int jj = 0; jj < 16; jj++) {
        int t = tid + jj * 256;
        float2 Gt = Gp[t];
        float2 Gr = Gp[(NFFT - t) & (NFFT - 1)];
        float Ax = 0.5f * (Gt.x + Gr.x), Ay = 0.5f * (Gt.y - Gr.y);
        float Dx = 0.5f * (Gt.x - Gr.x), Dy = 0.5f * (Gt.y + Gr.y);
        float Fx = par ? Dy : Ax;
        float Fy = par ? -Dx : Ay;
        float2 z = Z[IDX(t)];
        float pr = z.x * Fx - z.y * Fy;
        float pi = z.x * Fy + z.y * Fx;
        y[jj] = make_float2(pr, -pi);   // conj for IFFT-via-FFT
    }
    __syncthreads();
#pragma unroll
    for (int jj = 0; jj < 16; jj++) {
        int i = tid + jj * 256;
        Z[IDX(dr4(i))] = y[jj];
    }
    fft4096_r16(Z, TW);
    const float invN = 1.f / (float)NFFT;
    for (int t = tid; t < LSEQ; t += 256) {
        float2 w = Z[IDX(t)];
        g_kf[t * DMODEL + c] =  w.x * invN;   // Re(conj) = Re
        g_vf[t * DMODEL + c] = -w.y * invN;   // Im(conj) = -Im
    }
}

// ---------------- gates: g_l = relu(v_f^T (W .* scale) k_f + b)^2 + eps ----------------
__global__ void gates_kernel(const float* __restrict__ wgz_w, const float* __restrict__ wgz_b,
                             const float* __restrict__ scale) {
    __shared__ float Wsc[HD * HD];
    int tid = threadIdx.x;  // 256
    for (int i = tid; i < HD * HD; i += blockDim.x) Wsc[i] = wgz_w[i] * scale[i];
    __syncthreads();
    int w = tid >> 5, lane = tid & 31;
    int p = blockIdx.x * 8 + w;           // p = h*2048 + l
    int h = p >> 11, l = p & (LSEQ - 1);
    const float* vrow = g_vf + l * DMODEL + h * HD;
    const float* krow = g_kf + l * DMODEL + h * HD;
    float acc = 0.f;
#pragma unroll
    for (int eo = 0; eo < 2; eo++) {
        int e = lane + eo * 32;
        float inner = 0.f;
#pragma unroll 16
        for (int d = 0; d < 64; d++) inner += vrow[d] * Wsc[d * 64 + e];
        acc += krow[e] * inner;
    }
#pragma unroll
    for (int o = 16; o; o >>= 1) acc += __shfl_xor_sync(0xffffffffu, acc, o);
    if (lane == 0) {
        float lg = acc + wgz_b[0];
        float r = fmaxf(lg, 0.f);
        g_gate[p] = r * r + EPSF;
    }
}

// ---------------- per-chunk rank-1 sums: S_c[d,e] = sum_{l in chunk} g_l v_f[l,d] k_f[l,e] ----
__global__ void chunksum_kernel() {
    int hb = blockIdx.x;                  // h*16 + c
    int h = hb >> 4, c = hb & 15;
    int tid = threadIdx.x;                // 128
    int e = tid >> 1, half = tid & 1, d0 = half * 32;
    float acc[32];
#pragma unroll
    for (int j = 0; j < 32; j++) acc[j] = 0.f;
    int l0 = c * TCH;
    for (int i = 0; i < TCH; i++) {
        int l = l0 + i;
        float gg = g_gate[h * LSEQ + l];
        float ke = g_kf[l * DMODEL + h * HD + e];
        float gk = gg * ke;
        const float4* vp = reinterpret_cast<const float4*>(g_vf + l * DMODEL + h * HD + d0);
#pragma unroll
        for (int j4 = 0; j4 < 8; j4++) {
            float4 v4 = vp[j4];
            acc[j4 * 4 + 0] += gk * v4.x;
            acc[j4 * 4 + 1] += gk * v4.y;
            acc[j4 * 4 + 2] += gk * v4.z;
            acc[j4 * 4 + 3] += gk * v4.w;
        }
    }
    float* Sp = g_S + (size_t)hb * HD * HD;
#pragma unroll
    for (int j = 0; j < 32; j++) Sp[(d0 + j) * 64 + e] = acc[j];
}

// ---------------- exclusive prefix over chunks (state matrices + gate sums) ----------------
__global__ void prefix_kernel() {
    int h = blockIdx.x, tid = threadIdx.x;  // 512
    __shared__ float gc[NCHUNK];
    if (tid < NCHUNK) {
        float s = 0.f;
        for (int i = 0; i < TCH; i++) s += g_gate[h * LSEQ + tid * TCH + i];
        gc[tid] = s;
    }
    __syncthreads();
    if (tid == 0) {
        float run = 0.f;
        for (int c = 0; c < NCHUNK; c++) { float t = gc[c]; g_Gpre[h * NCHUNK + c] = run; run += t; }
    }
    for (int idx = tid; idx < HD * HD; idx += 512) {
        float run = 0.f;
#pragma unroll
        for (int c = 0; c < NCHUNK; c++) {
            size_t off = ((size_t)(h * NCHUNK + c)) * HD * HD + idx;
            float t = g_S[off];
            g_Spre[off] = run;
            run += t;
        }
    }
}

// ---------------- intra-chunk scan + readout (256 threads: 4 threads per column e) -------
__global__ void scan_readout_kernel(const float* __restrict__ scale) {
    extern __shared__ float sm[];
    float* qs = sm;                // 128*64
    float* ks = sm + 8192;
    float* vs = sm + 16384;
    float* gs = sm + 24576;        // 128
    int hb = blockIdx.x;
    int h = hb >> 4, c = hb & 15;
    int tid = threadIdx.x;         // 256
    int l0 = c * TCH;
    for (int idx = tid; idx < TCH * HD; idx += 256) {
        int row = idx >> 6, col = idx & 63;
        int ga = (l0 + row) * DMODEL + h * HD + col;
        qs[idx] = g_q[ga];
        ks[idx] = g_kf[ga];
        vs[idx] = g_vf[ga];
    }
    if (tid < TCH) gs[tid] = g_gate[h * LSEQ + l0 + tid];
    int e = tid >> 2, quarter = tid & 3, d0 = quarter * 16;
    float M[16], sc[16];
    {
        const float* Sp = g_Spre + (size_t)hb * HD * HD;
#pragma unroll
        for (int j = 0; j < 16; j++) {
            M[j]  = Sp[(d0 + j) * 64 + e];
            sc[j] = scale[(d0 + j) * 64 + e];
        }
    }
    float G = g_Gpre[h * NCHUNK + c];
    __syncthreads();
    const float4* q4 = reinterpret_cast<const float4*>(qs);
    const float4* v4 = reinterpret_cast<const float4*>(vs);
    int o4 = quarter * 4;
    for (int i = 0; i < TCH; i++) {
        float gg = gs[i]; G += gg;
        float ke = ks[i * HD + e];
        float gk = gg * ke;
        float r = 0.f;
#pragma unroll
        for (int j4 = 0; j4 < 4; j4++) {
            float4 vv = v4[i * 16 + o4 + j4];
            float4 qq = q4[i * 16 + o4 + j4];
            int jb = j4 * 4;
            M[jb + 0] += gk * vv.x; r += qq.x * (sc[jb + 0] * M[jb + 0]);
            M[jb + 1] += gk * vv.y; r += qq.y * (sc[jb + 1] * M[jb + 1]);
            M[jb + 2] += gk * vv.z; r += qq.z * (sc[jb + 2] * M[jb + 2]);
            M[jb + 3] += gk * vv.w; r += qq.w * (sc[jb + 3] * M[jb + 3]);
        }
        r += __shfl_xor_sync(0xffffffffu, r, 1);
        r += __shfl_xor_sync(0xffffffffu, r, 2);
        if (quarter == 0) g_sraw[(l0 + i) * DMODEL + h * HD + e] = r / fmaxf(G, EPSF);
    }
}

// ---------------- l2-normalize sp per (l, head), in place ----------------
__global__ void spnorm_kernel() {
    int tid = threadIdx.x;          // 256
    int w = tid >> 5, lane = tid & 31;
    int p = blockIdx.x * 8 + w;     // l*8 + h
    int l = p >> 3, h = p & 7;
    float* base = g_sraw + l * DMODEL + h * HD;
    float a = base[lane], b = base[lane + 32];
    float ss = a * a + b * b;
#pragma unroll
    for (int o = 16; o; o >>= 1) ss += __shfl_xor_sync(0xffffffffu, ss, o);
    float inv = 1.f / fmaxf(sqrtf(ss), EPSF);
    base[lane] = a * inv;
    base[lane + 32] = b * inv;
}

// ---------------- launch ----------------
extern "C" void kernel_launch(void* const* d_in, const int* in_sizes, int n_in,
                              void* d_out, int out_size) {
    const float* x     = (const float*)d_in[0];
    const float* sb    = (const float*)d_in[1];
    const float* wq_w  = (const float*)d_in[2];
    const float* wq_b  = (const float*)d_in[3];
    const float* wk_w  = (const float*)d_in[4];
    const float* wk_b  = (const float*)d_in[5];
    const float* wv_w  = (const float*)d_in[6];
    const float* wv_b  = (const float*)d_in[7];
    const float* wo_w  = (const float*)d_in[8];
    const float* wo_b  = (const float*)d_in[9];
    const float* td_w  = (const float*)d_in[10];
    const float* td_b  = (const float*)d_in[11];
    const float* wgz_w = (const float*)d_in[12];
    const float* wgz_b = (const float*)d_in[13];
    const float* kvs   = (const float*)d_in[14];
    float* out = (float*)d_out;

    float* sp;
    cudaGetSymbolAddress((void**)&sp, g_sraw);

    cudaFuncSetAttribute(filtfft_kernel, cudaFuncAttributeMaxDynamicSharedMemorySize, FFT_SMEM);
    cudaFuncSetAttribute(fftconv_kernel, cudaFuncAttributeMaxDynamicSharedMemorySize, FFT_SMEM);
    cudaFuncSetAttribute(scan_readout_kernel, cudaFuncAttributeMaxDynamicSharedMemorySize, 98816);

    dim3 g4(DMODEL / 64, LSEQ / 64, 4);
    gemm4_kernel<<<g4, 256>>>(x, sb, wq_w, wk_w, wv_w, td_w, wq_b, wk_b, wv_b, td_b);
    filtfft_kernel<<<DMODEL / 2, 256, FFT_SMEM>>>();
    fftconv_kernel<<<DMODEL, 256, FFT_SMEM>>>();
    gates_kernel<<<(NH * LSEQ) / 8, 256>>>(wgz_w, wgz_b, kvs);
    chunksum_kernel<<<NH * NCHUNK, 128>>>();
    prefix_kernel<<<NH, 512>>>();
    scan_readout_kernel<<<NH * NCHUNK, 256, 98816>>>(kvs);
    spnorm_kernel<<<(LSEQ * NH) / 8, 256>>>();
    dim3 g1(DMODEL / 64, LSEQ / 64, 1);
    gemm1_kernel<<<g1, 256>>>(sp, wo_w, wo_b, out);
}